// round 14
// baseline (speedup 1.0000x reference)
#include <cuda_runtime.h>
#include <math.h>

// Problem constants
#define N_B    16
#define C_IN   512
#define C4     128
#define QKC    16
#define HDIM   32
#define LPIX   1024
#define NSCALE 3
#define EPSBN  1e-5f

// ---------------- device scratch (no allocation allowed) ----------------
__device__ float g_value[N_B * C4 * LPIX];              // 8 MB
__device__ float g_q[N_B * NSCALE * QKC * LPIX];        // 3 MB
__device__ float g_k[N_B * NSCALE * QKC * LPIX];        // 3 MB
__device__ float g_cat[N_B * NSCALE * C4 * LPIX];       // 24 MB
__device__ float g_y[N_B * C_IN * LPIX];                // 32 MB
__device__ float g_wt[9 * 384 * 512];                   // 7 MB transformed weights (tf32)
__device__ float g_mean[C_IN];
__device__ float g_rstd[C_IN];

// ---------------- tf32 helpers ----------------
__device__ __forceinline__ float tf32r(float x) {
    float r;
    asm("cvt.rna.tf32.f32 %0, %1;" : "=f"(r) : "f"(x));
    return r;
}

__device__ __forceinline__ void mma_tf32(float* d, const float* a, float b0, float b1) {
    asm volatile(
        "mma.sync.aligned.m16n8k8.row.col.f32.tf32.tf32.f32 "
        "{%0,%1,%2,%3}, {%4,%5,%6,%7}, {%8,%9}, {%0,%1,%2,%3};"
        : "+f"(d[0]), "+f"(d[1]), "+f"(d[2]), "+f"(d[3])
        : "r"(__float_as_uint(a[0])), "r"(__float_as_uint(a[1])),
          "r"(__float_as_uint(a[2])), "r"(__float_as_uint(a[3])),
          "r"(__float_as_uint(b0)),  "r"(__float_as_uint(b1)));
}

// =========================================================================
// Kernel 1: value projection  g_value[n][o][l] = value_w(128x512) @ x[n] + b
// =========================================================================
__global__ __launch_bounds__(256) void value_proj_kernel(
    const float* __restrict__ x, const float* __restrict__ w,
    const float* __restrict__ bias)
{
    const int lb = blockIdx.x * 64;
    const int ob = blockIdx.y * 64;
    const int n  = blockIdx.z;

    __shared__ float a_s[16][65];   // [kk][oo]
    __shared__ float b_s[16][65];   // [kk][ll]

    const float* xb = x + (size_t)n * C_IN * LPIX;
    const int tid = threadIdx.x;
    const int tx = tid & 15, ty = tid >> 4;

    float acc[4][4];
#pragma unroll
    for (int i = 0; i < 4; i++)
#pragma unroll
        for (int j = 0; j < 4; j++) acc[i][j] = 0.f;

    for (int k0 = 0; k0 < C_IN; k0 += 16) {
        {
            int oo = tid >> 2, kk = (tid & 3) * 4;
            const float* wp = &w[(size_t)(ob + oo) * C_IN + k0 + kk];
            float4 v = *(const float4*)wp;
            a_s[kk + 0][oo] = v.x; a_s[kk + 1][oo] = v.y;
            a_s[kk + 2][oo] = v.z; a_s[kk + 3][oo] = v.w;
        }
        {
            int kk = tid >> 4, ll = (tid & 15) * 4;
            const float4 v = *(const float4*)&xb[(size_t)(k0 + kk) * LPIX + lb + ll];
            b_s[kk][ll + 0] = v.x; b_s[kk][ll + 1] = v.y;
            b_s[kk][ll + 2] = v.z; b_s[kk][ll + 3] = v.w;
        }
        __syncthreads();
#pragma unroll
        for (int kk = 0; kk < 16; kk++) {
            float av[4], bv[4];
#pragma unroll
            for (int i = 0; i < 4; i++) av[i] = a_s[kk][ty * 4 + i];
#pragma unroll
            for (int j = 0; j < 4; j++) bv[j] = b_s[kk][tx * 4 + j];
#pragma unroll
            for (int i = 0; i < 4; i++)
#pragma unroll
                for (int j = 0; j < 4; j++) acc[i][j] += av[i] * bv[j];
        }
        __syncthreads();
    }

#pragma unroll
    for (int i = 0; i < 4; i++) {
        int o = ob + ty * 4 + i;
        float bb = bias[o];
        float* op = &g_value[((size_t)n * C4 + o) * LPIX + lb + tx * 4];
#pragma unroll
        for (int j = 0; j < 4; j++) op[j] = acc[i][j] + bb;
    }
}

// =========================================================================
// Kernel 2: pyramid pool -> rce conv -> q/k proj -> bilinear upsample
// =========================================================================
__global__ __launch_bounds__(256) void pyramid_kernel(
    const float* __restrict__ x,
    const float* __restrict__ rce_w, const float* __restrict__ rce_b,
    const float* __restrict__ q_w,   const float* __restrict__ q_b,
    const float* __restrict__ k_w,   const float* __restrict__ k_b)
{
    const int n = blockIdx.x, s = blockIdx.y;
    const int sz = 1 << s;            // 1, 2, 4
    const int bs = HDIM / sz;
    const int cells = sz * sz;
    const int tid = threadIdx.x;

    __shared__ float pooled_s[512 * 16];
    __shared__ float feat_s[128 * 16];
    __shared__ float qf_s[16 * 16];
    __shared__ float kf_s[16 * 16];

    // adaptive avg pool
    for (int c = tid; c < C_IN; c += 256) {
        const float* xp = x + ((size_t)n * C_IN + c) * LPIX;
        for (int ci = 0; ci < sz; ci++)
            for (int cj = 0; cj < sz; cj++) {
                float sum = 0.f;
                for (int a = 0; a < bs; a++) {
                    const float* rp = xp + (ci * bs + a) * HDIM + cj * bs;
                    for (int b = 0; b < bs; b++) sum += rp[b];
                }
                pooled_s[c * 16 + ci * sz + cj] = sum / (float)(bs * bs);
            }
    }
    __syncthreads();

    // rce 1x1 conv: C_IN -> C4 on pooled grid
    for (int idx = tid; idx < 128 * cells; idx += 256) {
        int o = idx & 127, cell = idx >> 7;
        const float* wp = rce_w + ((size_t)s * C4 + o) * C_IN;
        float sum = rce_b[s * C4 + o];
        for (int c = 0; c < C_IN; c++) sum += wp[c] * pooled_s[c * 16 + cell];
        feat_s[o * 16 + cell] = sum;
    }
    __syncthreads();

    // q/k 1x1 conv on pooled grid (commutes with upsample)
    for (int idx = tid; idx < QKC * cells; idx += 256) {
        int qc = idx & 15, cell = idx >> 4;
        const float* qwp = q_w + qc * C4;
        const float* kwp = k_w + qc * C4;
        float sq = q_b[qc], sk = k_b[qc];
        for (int c = 0; c < C4; c++) {
            float f = feat_s[c * 16 + cell];
            sq += qwp[c] * f;
            sk += kwp[c] * f;
        }
        qf_s[qc * 16 + cell] = sq;
        kf_s[qc * 16 + cell] = sk;
    }
    __syncthreads();

    // bilinear upsample (align_corners=True) to 32x32, write q/k
    float* gqb = g_q + (size_t)(n * NSCALE + s) * QKC * LPIX;
    float* gkb = g_k + (size_t)(n * NSCALE + s) * QKC * LPIX;

    for (int l = tid; l < LPIX; l += 256) {
        int o = l >> 5, p = l & 31;
        int io = 0, jo = 0;
        float fo = 0.f, fp = 0.f;
        if (sz > 1) {
            float pos = (float)o * (float)(sz - 1) / 31.0f;
            io = (int)pos; if (io > sz - 2) io = sz - 2;
            fo = pos - (float)io;
            pos = (float)p * (float)(sz - 1) / 31.0f;
            jo = (int)pos; if (jo > sz - 2) jo = sz - 2;
            fp = pos - (float)jo;
        }
        for (int qc = 0; qc < QKC; qc++) {
            float vq, vk;
            if (sz == 1) {
                vq = qf_s[qc * 16];
                vk = kf_s[qc * 16];
            } else {
                const float* f = &qf_s[qc * 16];
                float top = (1.f - fp) * f[io * sz + jo] + fp * f[io * sz + jo + 1];
                float bot = (1.f - fp) * f[(io + 1) * sz + jo] + fp * f[(io + 1) * sz + jo + 1];
                vq = (1.f - fo) * top + fo * bot;
                const float* g = &kf_s[qc * 16];
                top = (1.f - fp) * g[io * sz + jo] + fp * g[io * sz + jo + 1];
                bot = (1.f - fp) * g[(io + 1) * sz + jo] + fp * g[(io + 1) * sz + jo + 1];
                vk = (1.f - fo) * top + fo * bot;
            }
            gqb[qc * LPIX + l] = vq;
            gkb[qc * LPIX + l] = vk;
        }
    }
}

// =========================================================================
// Kernel 3: fused attention, tf32 mma, warp-owns-rows flash softmax.
// Block = 128 query rows; warp w owns rows [w*16, w*16+16) exclusively ->
// row max/sum/alpha are warp-local (quad shfl), P via warp-private smem
// strip + __syncwarp(). Only 2 __syncthreads per L-chunk (k/v staging).
// grid: (8 m-tiles, 3 scales, 16 batches), 256 threads.
// =========================================================================
__global__ __launch_bounds__(256) void attn_mma_kernel()
{
    const int m0 = blockIdx.x * 128;
    const int s  = blockIdx.y;
    const int n  = blockIdx.z;
    const int tid  = threadIdx.x;
    const int w    = tid >> 5;
    const int lane = tid & 31;
    const int g = lane >> 2, q = lane & 3;

    __shared__ float sm[9856];            // 39.4 KB
    float* k_s = sm;                      // [16][40]
    float* v_s = sm + 640;                // [128][36]
    float* p_s = sm + 5248;               // [128][36] (warp strips of 16 rows)
    float* out_s = sm;                    // alias [128][66] for epilogue

    const float* qb = g_q + (size_t)(n * NSCALE + s) * QKC * LPIX;
    const float* kb = g_k + (size_t)(n * NSCALE + s) * QKC * LPIX;
    const float* vb = g_value + (size_t)n * C4 * LPIX;

    // persistent q A-fragments for this warp's 16 rows (2 k-steps)
    const int rlo = m0 + w * 16 + g;
    float qa[2][4];
#pragma unroll
    for (int ks = 0; ks < 2; ks++) {
        qa[ks][0] = tf32r(qb[(ks * 8 + q) * LPIX + rlo]);
        qa[ks][1] = tf32r(qb[(ks * 8 + q) * LPIX + rlo + 8]);
        qa[ks][2] = tf32r(qb[(ks * 8 + q + 4) * LPIX + rlo]);
        qa[ks][3] = tf32r(qb[(ks * 8 + q + 4) * LPIX + rlo + 8]);
    }

    float M0 = -1e30f, M1 = -1e30f, S0 = 0.f, S1 = 0.f;
    float acc[16][4];
#pragma unroll
    for (int nt = 0; nt < 16; nt++)
#pragma unroll
        for (int r = 0; r < 4; r++) acc[nt][r] = 0.f;

    float* pw = p_s + w * 16 * 36;        // warp-private P strip

    for (int l0 = 0; l0 < LPIX; l0 += 32) {
        __syncthreads();                  // protect k_s/v_s from prev iter
        // ---- stage k [16][32] and v [128][32], float4, tf32-rounded ----
        if (tid < 128) {
            int kc = tid >> 3, l4 = (tid & 7) * 4;
            float4 t = *(const float4*)&kb[kc * LPIX + l0 + l4];
            float4 r4 = make_float4(tf32r(t.x), tf32r(t.y), tf32r(t.z), tf32r(t.w));
            *(float4*)&k_s[kc * 40 + l4] = r4;
        }
#pragma unroll
        for (int e = tid; e < 1024; e += 256) {
            int c = e >> 3, l4 = (e & 7) * 4;
            float4 t = *(const float4*)&vb[(size_t)c * LPIX + l0 + l4];
            float4 r4 = make_float4(tf32r(t.x), tf32r(t.y), tf32r(t.z), tf32r(t.w));
            *(float4*)&v_s[c * 36 + l4] = r4;
        }
        __syncthreads();

        // ---- QK: this warp's 16 rows x all 32 l-cols (4 n-tiles) ----
        float sacc[4][4];
#pragma unroll
        for (int nt = 0; nt < 4; nt++) {
            sacc[nt][0] = sacc[nt][1] = sacc[nt][2] = sacc[nt][3] = 0.f;
#pragma unroll
            for (int ks = 0; ks < 2; ks++) {
                float b0 = k_s[(ks * 8 + q) * 40 + nt * 8 + g];
                float b1 = k_s[(ks * 8 + q + 4) * 40 + nt * 8 + g];
                mma_tf32(sacc[nt], qa[ks], b0, b1);
            }
        }

        // ---- warp-local row max via quad shfl ----
        float mx0 = -1e30f, mx1 = -1e30f;
#pragma unroll
        for (int nt = 0; nt < 4; nt++) {
            mx0 = fmaxf(mx0, fmaxf(sacc[nt][0], sacc[nt][1]));
            mx1 = fmaxf(mx1, fmaxf(sacc[nt][2], sacc[nt][3]));
        }
        mx0 = fmaxf(mx0, __shfl_xor_sync(0xffffffffu, mx0, 1));
        mx0 = fmaxf(mx0, __shfl_xor_sync(0xffffffffu, mx0, 2));
        mx1 = fmaxf(mx1, __shfl_xor_sync(0xffffffffu, mx1, 1));
        mx1 = fmaxf(mx1, __shfl_xor_sync(0xffffffffu, mx1, 2));

        float Mn0 = fmaxf(M0, mx0), Mn1 = fmaxf(M1, mx1);
        float a0 = __expf(M0 - Mn0), a1 = __expf(M1 - Mn1);
        M0 = Mn0; M1 = Mn1;

        // ---- exp, write P to warp strip, row sums ----
        float ps0 = 0.f, ps1 = 0.f;
#pragma unroll
        for (int nt = 0; nt < 4; nt++) {
            float e00 = __expf(sacc[nt][0] - M0);
            float e01 = __expf(sacc[nt][1] - M0);
            float e10 = __expf(sacc[nt][2] - M1);
            float e11 = __expf(sacc[nt][3] - M1);
            ps0 += e00 + e01;
            ps1 += e10 + e11;
            int col = nt * 8 + 2 * q;
            *(float2*)&pw[g * 36 + col]       = make_float2(tf32r(e00), tf32r(e01));
            *(float2*)&pw[(g + 8) * 36 + col] = make_float2(tf32r(e10), tf32r(e11));
        }
        ps0 += __shfl_xor_sync(0xffffffffu, ps0, 1);
        ps0 += __shfl_xor_sync(0xffffffffu, ps0, 2);
        ps1 += __shfl_xor_sync(0xffffffffu, ps1, 1);
        ps1 += __shfl_xor_sync(0xffffffffu, ps1, 2);
        S0 = S0 * a0 + ps0;
        S1 = S1 * a1 + ps1;

        // ---- rescale accumulators ----
#pragma unroll
        for (int nt = 0; nt < 16; nt++) {
            acc[nt][0] *= a0; acc[nt][1] *= a0;
            acc[nt][2] *= a1; acc[nt][3] *= a1;
        }
        __syncwarp();

        // ---- PV: D[16m x 128c] per warp ----
#pragma unroll
        for (int ks = 0; ks < 4; ks++) {
            float pa[4];
            pa[0] = pw[g * 36 + ks * 8 + q];
            pa[1] = pw[(g + 8) * 36 + ks * 8 + q];
            pa[2] = pw[g * 36 + ks * 8 + q + 4];
            pa[3] = pw[(g + 8) * 36 + ks * 8 + q + 4];
#pragma unroll
            for (int nt = 0; nt < 16; nt++) {
                float b0 = v_s[(nt * 8 + g) * 36 + ks * 8 + q];
                float b1 = v_s[(nt * 8 + g) * 36 + ks * 8 + q + 4];
                mma_tf32(acc[nt], pa, b0, b1);
            }
        }
    }

    // ---- epilogue: normalize, transpose via smem in 2 waves ----
    float il = 1.f / S0, ih = 1.f / S1;
    float* cb = g_cat + ((size_t)n * (NSCALE * C4) + s * C4) * LPIX + m0;
#pragma unroll
    for (int wave = 0; wave < 2; wave++) {
        __syncthreads();     // smem free (prev wave copy / main loop done)
        if ((w >> 2) == wave) {
            int lm = (w & 3) * 16 + g;        // 0..63 within wave
#pragma unroll
            for (int nt = 0; nt < 16; nt++) {
                int c = nt * 8 + 2 * q;
                out_s[(size_t)c * 66 + lm]       = acc[nt][0] * il;
                out_s[(size_t)(c + 1) * 66 + lm] = acc[nt][1] * il;
                out_s[(size_t)c * 66 + lm + 8]       = acc[nt][2] * ih;
                out_s[(size_t)(c + 1) * 66 + lm + 8] = acc[nt][3] * ih;
            }
        }
        __syncthreads();
        for (int e = tid; e < 8192; e += 256) {
            int c = e >> 6, m = e & 63;
            cb[(size_t)c * LPIX + wave * 64 + m] = out_s[c * 66 + m];
        }
    }
}

// =========================================================================
// Kernel 4a: weight transform  g_wt[p][ic][oc] = tf32(fusion_w[oc][ic][p])
// =========================================================================
__global__ __launch_bounds__(256) void wt_transform_kernel(const float* __restrict__ W)
{
    int idx = blockIdx.x * 256 + threadIdx.x;   // total 9*384*512 = 1769472
    if (idx >= 9 * 384 * 512) return;
    int oc = idx & 511;
    int t  = idx >> 9;
    int ic = t % 384;
    int p  = t / 384;
    g_wt[idx] = tf32r(W[(size_t)oc * 3456 + ic * 9 + p]);
}

// =========================================================================
// Kernel 4b: 3x3 fusion conv as implicit GEMM with tf32 mma.sync m16n8k8.
// =========================================================================
__global__ __launch_bounds__(256, 2) void conv_mma_kernel()
{
    const int ocb = blockIdx.x * 64;
    const int h0  = blockIdx.y * 8;
    const int n   = blockIdx.z;
    const int tid  = threadIdx.x;
    const int wid  = tid >> 5;
    const int lane = tid & 31;
    const int g = lane >> 2;       // group id 0..7
    const int q = lane & 3;        // thread-in-group 0..3
    const int wm = wid >> 2;       // 0..1 (oc)
    const int wn = wid & 3;        // 0..3 (pixel rows pair)

    __shared__ float in_s[8 * 344];      // [ic 8][(row 10)*(col 34) pad 344]
    __shared__ float a_s[9 * 64 * 12];   // [p 9][oc 64][ic 8 pad 12]

    float acc[2][8][4];
#pragma unroll
    for (int mt = 0; mt < 2; mt++)
#pragma unroll
        for (int nt = 0; nt < 8; nt++)
#pragma unroll
            for (int r = 0; r < 4; r++) acc[mt][nt][r] = 0.f;

    const float* catn = g_cat + (size_t)n * (NSCALE * C4) * LPIX;

    for (int ic0 = 0; ic0 < 384; ic0 += 8) {
        for (int e = tid; e < 8 * 340; e += 256) {
            int ic  = e / 340;
            int rem = e - ic * 340;
            int rr  = rem / 34;
            int cc  = rem - rr * 34;
            int gh = h0 + rr - 1, gw = cc - 1;
            float v = 0.f;
            if ((unsigned)gh < 32u && (unsigned)gw < 32u)
                v = catn[(size_t)(ic0 + ic) * LPIX + gh * HDIM + gw];
            in_s[ic * 344 + rem] = tf32r(v);
        }
        for (int e = tid; e < 4608; e += 256) {
            int o = e & 63;
            int t = e >> 6;
            int i = t & 7;
            int p = t >> 3;
            a_s[(p * 64 + o) * 12 + i] = g_wt[((size_t)p * 384 + ic0 + i) * 512 + ocb + o];
        }
        __syncthreads();

#pragma unroll
        for (int p = 0; p < 9; p++) {
            const int kh = p / 3, kw = p - kh * 3;
            float afr[2][4];
#pragma unroll
            for (int mt = 0; mt < 2; mt++) {
                const float* ab = &a_s[(p * 64 + wm * 32 + mt * 16) * 12];
                afr[mt][0] = ab[g * 12 + q];
                afr[mt][1] = ab[(g + 8) * 12 + q];
                afr[mt][2] = ab[g * 12 + q + 4];
                afr[mt][3] = ab[(g + 8) * 12 + q + 4];
            }
#pragma unroll
            for (int nt = 0; nt < 8; nt++) {
                const int lh = wn * 2 + (nt >> 2);
                const int off = (lh + kh) * 34 + (nt & 3) * 8 + g + kw;
                float b0 = in_s[q * 344 + off];
                float b1 = in_s[(q + 4) * 344 + off];
                mma_tf32(acc[0][nt], afr[0], b0, b1);
                mma_tf32(acc[1][nt], afr[1], b0, b1);
            }
        }
        __syncthreads();
    }

    float* yb = g_y + (size_t)n * C_IN * LPIX;
#pragma unroll
    for (int mt = 0; mt < 2; mt++) {
        int oc0 = ocb + wm * 32 + mt * 16 + g;
#pragma unroll
        for (int nt = 0; nt < 8; nt++) {
            int px = h0 * HDIM + wn * 64 + nt * 8 + 2 * q;
            *(float2*)&yb[(size_t)oc0 * LPIX + px] =
                make_float2(acc[mt][nt][0], acc[mt][nt][1]);
            *(float2*)&yb[(size_t)(oc0 + 8) * LPIX + px] =
                make_float2(acc[mt][nt][2], acc[mt][nt][3]);
        }
    }
}

// =========================================================================
// Kernel 5: BN batch stats per channel (over N,H,W = 16384 values)
// =========================================================================
__global__ __launch_bounds__(256) void bn_stats_kernel(const float* __restrict__ bn_scale)
{
    const int c = blockIdx.x;
    const int tid = threadIdx.x;
    float s = 0.f, sq = 0.f;
    for (int n = 0; n < N_B; n++) {
        const float* p = g_y + ((size_t)n * C_IN + c) * LPIX;
        for (int l = tid; l < LPIX; l += 256) {
            float v = p[l];
            s += v;
            sq += v * v;
        }
    }
    __shared__ float r1[256], r2[256];
    r1[tid] = s; r2[tid] = sq;
    __syncthreads();
    for (int off = 128; off > 0; off >>= 1) {
        if (tid < off) { r1[tid] += r1[tid + off]; r2[tid] += r2[tid + off]; }
        __syncthreads();
    }
    if (tid == 0) {
        float m = r1[0] / 16384.f;
        float var = r2[0] / 16384.f - m * m;
        g_mean[c] = m;
        g_rstd[c] = bn_scale[c] / sqrtf(var + EPSBN);
    }
}

// =========================================================================
// Kernel 6: BN apply + ReLU + gamma*y + x   (float4 elementwise)
// =========================================================================
__global__ __launch_bounds__(256) void final_kernel(
    const float* __restrict__ x, const float* __restrict__ bn_bias,
    const float* __restrict__ gammap, float* __restrict__ out)
{
    const float gamma = gammap[0];
    int idx4 = blockIdx.x * blockDim.x + threadIdx.x;   // 2097152 total
    int c = (idx4 >> 8) & 511;
    float mean = g_mean[c], rstd = g_rstd[c], bias = bn_bias[c];
    float4 y = *(const float4*)&g_y[(size_t)idx4 * 4];
    float4 xv = *(const float4*)&x[(size_t)idx4 * 4];
    float4 o;
    o.x = gamma * fmaxf((y.x - mean) * rstd + bias, 0.f) + xv.x;
    o.y = gamma * fmaxf((y.y - mean) * rstd + bias, 0.f) + xv.y;
    o.z = gamma * fmaxf((y.z - mean) * rstd + bias, 0.f) + xv.z;
    o.w = gamma * fmaxf((y.w - mean) * rstd + bias, 0.f) + xv.w;
    *(float4*)&out[(size_t)idx4 * 4] = o;
}

// =========================================================================
extern "C" void kernel_launch(void* const* d_in, const int* in_sizes, int n_in,
                              void* d_out, int out_size)
{
    const float* x        = (const float*)d_in[0];
    const float* rce_w    = (const float*)d_in[1];
    const float* rce_b    = (const float*)d_in[2];
    const float* q_w      = (const float*)d_in[3];
    const float* q_b      = (const float*)d_in[4];
    const float* k_w      = (const float*)d_in[5];
    const float* k_b      = (const float*)d_in[6];
    const float* value_w  = (const float*)d_in[7];
    const float* value_b  = (const float*)d_in[8];
    const float* fusion_w = (const float*)d_in[9];
    const float* bn_scale = (const float*)d_in[10];
    const float* bn_bias  = (const float*)d_in[11];
    const float* gamma    = (const float*)d_in[12];
    float* out = (float*)d_out;

    value_proj_kernel<<<dim3(16, 2, 16), 256>>>(x, value_w, value_b);
    pyramid_kernel<<<dim3(16, 3), 256>>>(x, rce_w, rce_b, q_w, q_b, k_w, k_b);
    wt_transform_kernel<<<dim3((9 * 384 * 512 + 255) / 256), 256>>>(fusion_w);
    attn_mma_kernel<<<dim3(8, 3, 16), 256>>>();
    conv_mma_kernel<<<dim3(8, 4, 16), 256>>>();
    bn_stats_kernel<<<dim3(512), 256>>>(bn_scale);
    final_kernel<<<dim3(8192), 256>>>(x, bn_bias, gamma, out);
}

// round 15
// speedup vs baseline: 1.0003x; 1.0003x over previous
#include <cuda_runtime.h>
#include <math.h>

// Problem constants
#define N_B    16
#define C_IN   512
#define C4     128
#define QKC    16
#define HDIM   32
#define LPIX   1024
#define NSCALE 3
#define EPSBN  1e-5f

// ---------------- device scratch (no allocation allowed) ----------------
__device__ float g_value[N_B * C4 * LPIX];              // 8 MB
__device__ float g_q[N_B * NSCALE * QKC * LPIX];        // 3 MB
__device__ float g_k[N_B * NSCALE * QKC * LPIX];        // 3 MB
__device__ float g_cat[N_B * NSCALE * C4 * LPIX];       // 24 MB
__device__ float g_y[N_B * C_IN * LPIX];                // 32 MB
__device__ float g_wt[9 * 384 * 512];                   // 7 MB transformed weights (tf32)
__device__ float g_mean[C_IN];
__device__ float g_rstd[C_IN];

// ---------------- tf32 helpers ----------------
__device__ __forceinline__ float tf32r(float x) {
    float r;
    asm("cvt.rna.tf32.f32 %0, %1;" : "=f"(r) : "f"(x));
    return r;
}

__device__ __forceinline__ void mma_tf32(float* d, const float* a, float b0, float b1) {
    asm volatile(
        "mma.sync.aligned.m16n8k8.row.col.f32.tf32.tf32.f32 "
        "{%0,%1,%2,%3}, {%4,%5,%6,%7}, {%8,%9}, {%0,%1,%2,%3};"
        : "+f"(d[0]), "+f"(d[1]), "+f"(d[2]), "+f"(d[3])
        : "r"(__float_as_uint(a[0])), "r"(__float_as_uint(a[1])),
          "r"(__float_as_uint(a[2])), "r"(__float_as_uint(a[3])),
          "r"(__float_as_uint(b0)),  "r"(__float_as_uint(b1)));
}

// =========================================================================
// Kernel 1: value projection  g_value[n][o][l] = value_w(128x512) @ x[n] + b
// =========================================================================
__global__ __launch_bounds__(256) void value_proj_kernel(
    const float* __restrict__ x, const float* __restrict__ w,
    const float* __restrict__ bias)
{
    const int lb = blockIdx.x * 64;
    const int ob = blockIdx.y * 64;
    const int n  = blockIdx.z;

    __shared__ float a_s[16][65];   // [kk][oo]
    __shared__ float b_s[16][65];   // [kk][ll]

    const float* xb = x + (size_t)n * C_IN * LPIX;
    const int tid = threadIdx.x;
    const int tx = tid & 15, ty = tid >> 4;

    float acc[4][4];
#pragma unroll
    for (int i = 0; i < 4; i++)
#pragma unroll
        for (int j = 0; j < 4; j++) acc[i][j] = 0.f;

    for (int k0 = 0; k0 < C_IN; k0 += 16) {
        {
            int oo = tid >> 2, kk = (tid & 3) * 4;
            const float* wp = &w[(size_t)(ob + oo) * C_IN + k0 + kk];
            float4 v = *(const float4*)wp;
            a_s[kk + 0][oo] = v.x; a_s[kk + 1][oo] = v.y;
            a_s[kk + 2][oo] = v.z; a_s[kk + 3][oo] = v.w;
        }
        {
            int kk = tid >> 4, ll = (tid & 15) * 4;
            const float4 v = *(const float4*)&xb[(size_t)(k0 + kk) * LPIX + lb + ll];
            b_s[kk][ll + 0] = v.x; b_s[kk][ll + 1] = v.y;
            b_s[kk][ll + 2] = v.z; b_s[kk][ll + 3] = v.w;
        }
        __syncthreads();
#pragma unroll
        for (int kk = 0; kk < 16; kk++) {
            float av[4], bv[4];
#pragma unroll
            for (int i = 0; i < 4; i++) av[i] = a_s[kk][ty * 4 + i];
#pragma unroll
            for (int j = 0; j < 4; j++) bv[j] = b_s[kk][tx * 4 + j];
#pragma unroll
            for (int i = 0; i < 4; i++)
#pragma unroll
                for (int j = 0; j < 4; j++) acc[i][j] += av[i] * bv[j];
        }
        __syncthreads();
    }

#pragma unroll
    for (int i = 0; i < 4; i++) {
        int o = ob + ty * 4 + i;
        float bb = bias[o];
        float* op = &g_value[((size_t)n * C4 + o) * LPIX + lb + tx * 4];
#pragma unroll
        for (int j = 0; j < 4; j++) op[j] = acc[i][j] + bb;
    }
}

// =========================================================================
// Kernel 2: pyramid pool -> rce conv -> q/k proj -> bilinear upsample
// =========================================================================
__global__ __launch_bounds__(256) void pyramid_kernel(
    const float* __restrict__ x,
    const float* __restrict__ rce_w, const float* __restrict__ rce_b,
    const float* __restrict__ q_w,   const float* __restrict__ q_b,
    const float* __restrict__ k_w,   const float* __restrict__ k_b)
{
    const int n = blockIdx.x, s = blockIdx.y;
    const int sz = 1 << s;            // 1, 2, 4
    const int bs = HDIM / sz;
    const int cells = sz * sz;
    const int tid = threadIdx.x;

    __shared__ float pooled_s[512 * 16];
    __shared__ float feat_s[128 * 16];
    __shared__ float qf_s[16 * 16];
    __shared__ float kf_s[16 * 16];

    // adaptive avg pool
    for (int c = tid; c < C_IN; c += 256) {
        const float* xp = x + ((size_t)n * C_IN + c) * LPIX;
        for (int ci = 0; ci < sz; ci++)
            for (int cj = 0; cj < sz; cj++) {
                float sum = 0.f;
                for (int a = 0; a < bs; a++) {
                    const float* rp = xp + (ci * bs + a) * HDIM + cj * bs;
                    for (int b = 0; b < bs; b++) sum += rp[b];
                }
                pooled_s[c * 16 + ci * sz + cj] = sum / (float)(bs * bs);
            }
    }
    __syncthreads();

    // rce 1x1 conv: C_IN -> C4 on pooled grid
    for (int idx = tid; idx < 128 * cells; idx += 256) {
        int o = idx & 127, cell = idx >> 7;
        const float* wp = rce_w + ((size_t)s * C4 + o) * C_IN;
        float sum = rce_b[s * C4 + o];
        for (int c = 0; c < C_IN; c++) sum += wp[c] * pooled_s[c * 16 + cell];
        feat_s[o * 16 + cell] = sum;
    }
    __syncthreads();

    // q/k 1x1 conv on pooled grid (commutes with upsample)
    for (int idx = tid; idx < QKC * cells; idx += 256) {
        int qc = idx & 15, cell = idx >> 4;
        const float* qwp = q_w + qc * C4;
        const float* kwp = k_w + qc * C4;
        float sq = q_b[qc], sk = k_b[qc];
        for (int c = 0; c < C4; c++) {
            float f = feat_s[c * 16 + cell];
            sq += qwp[c] * f;
            sk += kwp[c] * f;
        }
        qf_s[qc * 16 + cell] = sq;
        kf_s[qc * 16 + cell] = sk;
    }
    __syncthreads();

    // bilinear upsample (align_corners=True) to 32x32, write q/k
    float* gqb = g_q + (size_t)(n * NSCALE + s) * QKC * LPIX;
    float* gkb = g_k + (size_t)(n * NSCALE + s) * QKC * LPIX;

    for (int l = tid; l < LPIX; l += 256) {
        int o = l >> 5, p = l & 31;
        int io = 0, jo = 0;
        float fo = 0.f, fp = 0.f;
        if (sz > 1) {
            float pos = (float)o * (float)(sz - 1) / 31.0f;
            io = (int)pos; if (io > sz - 2) io = sz - 2;
            fo = pos - (float)io;
            pos = (float)p * (float)(sz - 1) / 31.0f;
            jo = (int)pos; if (jo > sz - 2) jo = sz - 2;
            fp = pos - (float)jo;
        }
        for (int qc = 0; qc < QKC; qc++) {
            float vq, vk;
            if (sz == 1) {
                vq = qf_s[qc * 16];
                vk = kf_s[qc * 16];
            } else {
                const float* f = &qf_s[qc * 16];
                float top = (1.f - fp) * f[io * sz + jo] + fp * f[io * sz + jo + 1];
                float bot = (1.f - fp) * f[(io + 1) * sz + jo] + fp * f[(io + 1) * sz + jo + 1];
                vq = (1.f - fo) * top + fo * bot;
                const float* g = &kf_s[qc * 16];
                top = (1.f - fp) * g[io * sz + jo] + fp * g[io * sz + jo + 1];
                bot = (1.f - fp) * g[(io + 1) * sz + jo] + fp * g[(io + 1) * sz + jo + 1];
                vk = (1.f - fo) * top + fo * bot;
            }
            gqb[qc * LPIX + l] = vq;
            gkb[qc * LPIX + l] = vk;
        }
    }
}

// =========================================================================
// Kernel 3: fused attention, tf32 mma, warp-owns-rows flash softmax.
// Block = 128 query rows; warp w owns rows [w*16, w*16+16) exclusively ->
// row max/sum/alpha are warp-local (quad shfl), P via warp-private smem
// strip + __syncwarp(). Only 2 __syncthreads per L-chunk (k/v staging).
// grid: (8 m-tiles, 3 scales, 16 batches), 256 threads.
// =========================================================================
__global__ __launch_bounds__(256) void attn_mma_kernel()
{
    const int m0 = blockIdx.x * 128;
    const int s  = blockIdx.y;
    const int n  = blockIdx.z;
    const int tid  = threadIdx.x;
    const int w    = tid >> 5;
    const int lane = tid & 31;
    const int g = lane >> 2, q = lane & 3;

    __shared__ float sm[9856];            // 39.4 KB
    float* k_s = sm;                      // [16][40]
    float* v_s = sm + 640;                // [128][36]
    float* p_s = sm + 5248;               // [128][36] (warp strips of 16 rows)
    float* out_s = sm;                    // alias [128][66] for epilogue

    const float* qb = g_q + (size_t)(n * NSCALE + s) * QKC * LPIX;
    const float* kb = g_k + (size_t)(n * NSCALE + s) * QKC * LPIX;
    const float* vb = g_value + (size_t)n * C4 * LPIX;

    // persistent q A-fragments for this warp's 16 rows (2 k-steps)
    const int rlo = m0 + w * 16 + g;
    float qa[2][4];
#pragma unroll
    for (int ks = 0; ks < 2; ks++) {
        qa[ks][0] = tf32r(qb[(ks * 8 + q) * LPIX + rlo]);
        qa[ks][1] = tf32r(qb[(ks * 8 + q) * LPIX + rlo + 8]);
        qa[ks][2] = tf32r(qb[(ks * 8 + q + 4) * LPIX + rlo]);
        qa[ks][3] = tf32r(qb[(ks * 8 + q + 4) * LPIX + rlo + 8]);
    }

    float M0 = -1e30f, M1 = -1e30f, S0 = 0.f, S1 = 0.f;
    float acc[16][4];
#pragma unroll
    for (int nt = 0; nt < 16; nt++)
#pragma unroll
        for (int r = 0; r < 4; r++) acc[nt][r] = 0.f;

    float* pw = p_s + w * 16 * 36;        // warp-private P strip

    for (int l0 = 0; l0 < LPIX; l0 += 32) {
        __syncthreads();                  // protect k_s/v_s from prev iter
        // ---- stage k [16][32] and v [128][32], float4, tf32-rounded ----
        if (tid < 128) {
            int kc = tid >> 3, l4 = (tid & 7) * 4;
            float4 t = *(const float4*)&kb[kc * LPIX + l0 + l4];
            float4 r4 = make_float4(tf32r(t.x), tf32r(t.y), tf32r(t.z), tf32r(t.w));
            *(float4*)&k_s[kc * 40 + l4] = r4;
        }
#pragma unroll
        for (int e = tid; e < 1024; e += 256) {
            int c = e >> 3, l4 = (e & 7) * 4;
            float4 t = *(const float4*)&vb[(size_t)c * LPIX + l0 + l4];
            float4 r4 = make_float4(tf32r(t.x), tf32r(t.y), tf32r(t.z), tf32r(t.w));
            *(float4*)&v_s[c * 36 + l4] = r4;
        }
        __syncthreads();

        // ---- QK: this warp's 16 rows x all 32 l-cols (4 n-tiles) ----
        float sacc[4][4];
#pragma unroll
        for (int nt = 0; nt < 4; nt++) {
            sacc[nt][0] = sacc[nt][1] = sacc[nt][2] = sacc[nt][3] = 0.f;
#pragma unroll
            for (int ks = 0; ks < 2; ks++) {
                float b0 = k_s[(ks * 8 + q) * 40 + nt * 8 + g];
                float b1 = k_s[(ks * 8 + q + 4) * 40 + nt * 8 + g];
                mma_tf32(sacc[nt], qa[ks], b0, b1);
            }
        }

        // ---- warp-local row max via quad shfl ----
        float mx0 = -1e30f, mx1 = -1e30f;
#pragma unroll
        for (int nt = 0; nt < 4; nt++) {
            mx0 = fmaxf(mx0, fmaxf(sacc[nt][0], sacc[nt][1]));
            mx1 = fmaxf(mx1, fmaxf(sacc[nt][2], sacc[nt][3]));
        }
        mx0 = fmaxf(mx0, __shfl_xor_sync(0xffffffffu, mx0, 1));
        mx0 = fmaxf(mx0, __shfl_xor_sync(0xffffffffu, mx0, 2));
        mx1 = fmaxf(mx1, __shfl_xor_sync(0xffffffffu, mx1, 1));
        mx1 = fmaxf(mx1, __shfl_xor_sync(0xffffffffu, mx1, 2));

        float Mn0 = fmaxf(M0, mx0), Mn1 = fmaxf(M1, mx1);
        float a0 = __expf(M0 - Mn0), a1 = __expf(M1 - Mn1);
        M0 = Mn0; M1 = Mn1;

        // ---- exp, write P to warp strip, row sums ----
        float ps0 = 0.f, ps1 = 0.f;
#pragma unroll
        for (int nt = 0; nt < 4; nt++) {
            float e00 = __expf(sacc[nt][0] - M0);
            float e01 = __expf(sacc[nt][1] - M0);
            float e10 = __expf(sacc[nt][2] - M1);
            float e11 = __expf(sacc[nt][3] - M1);
            ps0 += e00 + e01;
            ps1 += e10 + e11;
            int col = nt * 8 + 2 * q;
            *(float2*)&pw[g * 36 + col]       = make_float2(tf32r(e00), tf32r(e01));
            *(float2*)&pw[(g + 8) * 36 + col] = make_float2(tf32r(e10), tf32r(e11));
        }
        ps0 += __shfl_xor_sync(0xffffffffu, ps0, 1);
        ps0 += __shfl_xor_sync(0xffffffffu, ps0, 2);
        ps1 += __shfl_xor_sync(0xffffffffu, ps1, 1);
        ps1 += __shfl_xor_sync(0xffffffffu, ps1, 2);
        S0 = S0 * a0 + ps0;
        S1 = S1 * a1 + ps1;

        // ---- rescale accumulators ----
#pragma unroll
        for (int nt = 0; nt < 16; nt++) {
            acc[nt][0] *= a0; acc[nt][1] *= a0;
            acc[nt][2] *= a1; acc[nt][3] *= a1;
        }
        __syncwarp();

        // ---- PV: D[16m x 128c] per warp ----
#pragma unroll
        for (int ks = 0; ks < 4; ks++) {
            float pa[4];
            pa[0] = pw[g * 36 + ks * 8 + q];
            pa[1] = pw[(g + 8) * 36 + ks * 8 + q];
            pa[2] = pw[g * 36 + ks * 8 + q + 4];
            pa[3] = pw[(g + 8) * 36 + ks * 8 + q + 4];
#pragma unroll
            for (int nt = 0; nt < 16; nt++) {
                float b0 = v_s[(nt * 8 + g) * 36 + ks * 8 + q];
                float b1 = v_s[(nt * 8 + g) * 36 + ks * 8 + q + 4];
                mma_tf32(acc[nt], pa, b0, b1);
            }
        }
    }

    // ---- epilogue: normalize, transpose via smem in 2 waves ----
    float il = 1.f / S0, ih = 1.f / S1;
    float* cb = g_cat + ((size_t)n * (NSCALE * C4) + s * C4) * LPIX + m0;
#pragma unroll
    for (int wave = 0; wave < 2; wave++) {
        __syncthreads();     // smem free (prev wave copy / main loop done)
        if ((w >> 2) == wave) {
            int lm = (w & 3) * 16 + g;        // 0..63 within wave
#pragma unroll
            for (int nt = 0; nt < 16; nt++) {
                int c = nt * 8 + 2 * q;
                out_s[(size_t)c * 66 + lm]       = acc[nt][0] * il;
                out_s[(size_t)(c + 1) * 66 + lm] = acc[nt][1] * il;
                out_s[(size_t)c * 66 + lm + 8]       = acc[nt][2] * ih;
                out_s[(size_t)(c + 1) * 66 + lm + 8] = acc[nt][3] * ih;
            }
        }
        __syncthreads();
        for (int e = tid; e < 8192; e += 256) {
            int c = e >> 6, m = e & 63;
            cb[(size_t)c * LPIX + wave * 64 + m] = out_s[c * 66 + m];
        }
    }
}

// =========================================================================
// Kernel 4a: weight transform  g_wt[p][ic][oc] = tf32(fusion_w[oc][ic][p])
// =========================================================================
__global__ __launch_bounds__(256) void wt_transform_kernel(const float* __restrict__ W)
{
    int idx = blockIdx.x * 256 + threadIdx.x;   // total 9*384*512 = 1769472
    if (idx >= 9 * 384 * 512) return;
    int oc = idx & 511;
    int t  = idx >> 9;
    int ic = t % 384;
    int p  = t / 384;
    g_wt[idx] = tf32r(W[(size_t)oc * 3456 + ic * 9 + p]);
}

// =========================================================================
// Kernel 4b: 3x3 fusion conv as implicit GEMM with tf32 mma.sync m16n8k8.
// =========================================================================
__global__ __launch_bounds__(256, 2) void conv_mma_kernel()
{
    const int ocb = blockIdx.x * 64;
    const int h0  = blockIdx.y * 8;
    const int n   = blockIdx.z;
    const int tid  = threadIdx.x;
    const int wid  = tid >> 5;
    const int lane = tid & 31;
    const int g = lane >> 2;       // group id 0..7
    const int q = lane & 3;        // thread-in-group 0..3
    const int wm = wid >> 2;       // 0..1 (oc)
    const int wn = wid & 3;        // 0..3 (pixel rows pair)

    __shared__ float in_s[8 * 344];      // [ic 8][(row 10)*(col 34) pad 344]
    __shared__ float a_s[9 * 64 * 12];   // [p 9][oc 64][ic 8 pad 12]

    float acc[2][8][4];
#pragma unroll
    for (int mt = 0; mt < 2; mt++)
#pragma unroll
        for (int nt = 0; nt < 8; nt++)
#pragma unroll
            for (int r = 0; r < 4; r++) acc[mt][nt][r] = 0.f;

    const float* catn = g_cat + (size_t)n * (NSCALE * C4) * LPIX;

    for (int ic0 = 0; ic0 < 384; ic0 += 8) {
        for (int e = tid; e < 8 * 340; e += 256) {
            int ic  = e / 340;
            int rem = e - ic * 340;
            int rr  = rem / 34;
            int cc  = rem - rr * 34;
            int gh = h0 + rr - 1, gw = cc - 1;
            float v = 0.f;
            if ((unsigned)gh < 32u && (unsigned)gw < 32u)
                v = catn[(size_t)(ic0 + ic) * LPIX + gh * HDIM + gw];
            in_s[ic * 344 + rem] = tf32r(v);
        }
        for (int e = tid; e < 4608; e += 256) {
            int o = e & 63;
            int t = e >> 6;
            int i = t & 7;
            int p = t >> 3;
            a_s[(p * 64 + o) * 12 + i] = g_wt[((size_t)p * 384 + ic0 + i) * 512 + ocb + o];
        }
        __syncthreads();

#pragma unroll
        for (int p = 0; p < 9; p++) {
            const int kh = p / 3, kw = p - kh * 3;
            float afr[2][4];
#pragma unroll
            for (int mt = 0; mt < 2; mt++) {
                const float* ab = &a_s[(p * 64 + wm * 32 + mt * 16) * 12];
                afr[mt][0] = ab[g * 12 + q];
                afr[mt][1] = ab[(g + 8) * 12 + q];
                afr[mt][2] = ab[g * 12 + q + 4];
                afr[mt][3] = ab[(g + 8) * 12 + q + 4];
            }
#pragma unroll
            for (int nt = 0; nt < 8; nt++) {
                const int lh = wn * 2 + (nt >> 2);
                const int off = (lh + kh) * 34 + (nt & 3) * 8 + g + kw;
                float b0 = in_s[q * 344 + off];
                float b1 = in_s[(q + 4) * 344 + off];
                mma_tf32(acc[0][nt], afr[0], b0, b1);
                mma_tf32(acc[1][nt], afr[1], b0, b1);
            }
        }
        __syncthreads();
    }

    float* yb = g_y + (size_t)n * C_IN * LPIX;
#pragma unroll
    for (int mt = 0; mt < 2; mt++) {
        int oc0 = ocb + wm * 32 + mt * 16 + g;
#pragma unroll
        for (int nt = 0; nt < 8; nt++) {
            int px = h0 * HDIM + wn * 64 + nt * 8 + 2 * q;
            *(float2*)&yb[(size_t)oc0 * LPIX + px] =
                make_float2(acc[mt][nt][0], acc[mt][nt][1]);
            *(float2*)&yb[(size_t)(oc0 + 8) * LPIX + px] =
                make_float2(acc[mt][nt][2], acc[mt][nt][3]);
        }
    }
}

// =========================================================================
// Kernel 5: BN batch stats per channel (over N,H,W = 16384 values)
// =========================================================================
__global__ __launch_bounds__(256) void bn_stats_kernel(const float* __restrict__ bn_scale)
{
    const int c = blockIdx.x;
    const int tid = threadIdx.x;
    float s = 0.f, sq = 0.f;
    for (int n = 0; n < N_B; n++) {
        const float* p = g_y + ((size_t)n * C_IN + c) * LPIX;
        for (int l = tid; l < LPIX; l += 256) {
            float v = p[l];
            s += v;
            sq += v * v;
        }
    }
    __shared__ float r1[256], r2[256];
    r1[tid] = s; r2[tid] = sq;
    __syncthreads();
    for (int off = 128; off > 0; off >>= 1) {
        if (tid < off) { r1[tid] += r1[tid + off]; r2[tid] += r2[tid + off]; }
        __syncthreads();
    }
    if (tid == 0) {
        float m = r1[0] / 16384.f;
        float var = r2[0] / 16384.f - m * m;
        g_mean[c] = m;
        g_rstd[c] = bn_scale[c] / sqrtf(var + EPSBN);
    }
}

// =========================================================================
// Kernel 6: BN apply + ReLU + gamma*y + x   (float4 elementwise)
// =========================================================================
__global__ __launch_bounds__(256) void final_kernel(
    const float* __restrict__ x, const float* __restrict__ bn_bias,
    const float* __restrict__ gammap, float* __restrict__ out)
{
    const float gamma = gammap[0];
    int idx4 = blockIdx.x * blockDim.x + threadIdx.x;   // 2097152 total
    int c = (idx4 >> 8) & 511;
    float mean = g_mean[c], rstd = g_rstd[c], bias = bn_bias[c];
    float4 y = *(const float4*)&g_y[(size_t)idx4 * 4];
    float4 xv = *(const float4*)&x[(size_t)idx4 * 4];
    float4 o;
    o.x = gamma * fmaxf((y.x - mean) * rstd + bias, 0.f) + xv.x;
    o.y = gamma * fmaxf((y.y - mean) * rstd + bias, 0.f) + xv.y;
    o.z = gamma * fmaxf((y.z - mean) * rstd + bias, 0.f) + xv.z;
    o.w = gamma * fmaxf((y.w - mean) * rstd + bias, 0.f) + xv.w;
    *(float4*)&out[(size_t)idx4 * 4] = o;
}

// =========================================================================
extern "C" void kernel_launch(void* const* d_in, const int* in_sizes, int n_in,
                              void* d_out, int out_size)
{
    const float* x        = (const float*)d_in[0];
    const float* rce_w    = (const float*)d_in[1];
    const float* rce_b    = (const float*)d_in[2];
    const float* q_w      = (const float*)d_in[3];
    const float* q_b      = (const float*)d_in[4];
    const float* k_w      = (const float*)d_in[5];
    const float* k_b      = (const float*)d_in[6];
    const float* value_w  = (const float*)d_in[7];
    const float* value_b  = (const float*)d_in[8];
    const float* fusion_w = (const float*)d_in[9];
    const float* bn_scale = (const float*)d_in[10];
    const float* bn_bias  = (const float*)d_in[11];
    const float* gamma    = (const float*)d_in[12];
    float* out = (float*)d_out;

    value_proj_kernel<<<dim3(16, 2, 16), 256>>>(x, value_w, value_b);
    pyramid_kernel<<<dim3(16, 3), 256>>>(x, rce_w, rce_b, q_w, q_b, k_w, k_b);
    wt_transform_kernel<<<dim3((9 * 384 * 512 + 255) / 256), 256>>>(fusion_w);
    attn_mma_kernel<<<dim3(8, 3, 16), 256>>>();
    conv_mma_kernel<<<dim3(8, 4, 16), 256>>>();
    bn_stats_kernel<<<dim3(512), 256>>>(bn_scale);
    final_kernel<<<dim3(8192), 256>>>(x, bn_bias, gamma, out);
}

// round 17
// speedup vs baseline: 1.0032x; 1.0029x over previous
#include <cuda_runtime.h>
#include <math.h>

// Problem constants
#define N_B    16
#define C_IN   512
#define C4     128
#define QKC    16
#define HDIM   32
#define LPIX   1024
#define NSCALE 3
#define EPSBN  1e-5f

// ---------------- device scratch (no allocation allowed) ----------------
__device__ float g_value[N_B * C4 * LPIX];              // 8 MB
__device__ float g_q[N_B * NSCALE * QKC * LPIX];        // 3 MB
__device__ float g_k[N_B * NSCALE * QKC * LPIX];        // 3 MB
__device__ float g_cat[N_B * NSCALE * C4 * LPIX];       // 24 MB
__device__ float g_y[N_B * C_IN * LPIX];                // 32 MB
__device__ float g_wt[9 * 384 * 512];                   // 7 MB transformed weights (tf32)
__device__ float g_mean[C_IN];
__device__ float g_rstd[C_IN];

// ---------------- tf32 helpers ----------------
__device__ __forceinline__ float tf32r(float x) {
    float r;
    asm("cvt.rna.tf32.f32 %0, %1;" : "=f"(r) : "f"(x));
    return r;
}

__device__ __forceinline__ void mma_tf32(float* d, const float* a, float b0, float b1) {
    asm volatile(
        "mma.sync.aligned.m16n8k8.row.col.f32.tf32.tf32.f32 "
        "{%0,%1,%2,%3}, {%4,%5,%6,%7}, {%8,%9}, {%0,%1,%2,%3};"
        : "+f"(d[0]), "+f"(d[1]), "+f"(d[2]), "+f"(d[3])
        : "r"(__float_as_uint(a[0])), "r"(__float_as_uint(a[1])),
          "r"(__float_as_uint(a[2])), "r"(__float_as_uint(a[3])),
          "r"(__float_as_uint(b0)),  "r"(__float_as_uint(b1)));
}

// =========================================================================
// Kernel 1: value projection  g_value[n][o][l] = value_w(128x512) @ x[n] + b
// =========================================================================
__global__ __launch_bounds__(256) void value_proj_kernel(
    const float* __restrict__ x, const float* __restrict__ w,
    const float* __restrict__ bias)
{
    const int lb = blockIdx.x * 64;
    const int ob = blockIdx.y * 64;
    const int n  = blockIdx.z;

    __shared__ float a_s[16][65];   // [kk][oo]
    __shared__ float b_s[16][65];   // [kk][ll]

    const float* xb = x + (size_t)n * C_IN * LPIX;
    const int tid = threadIdx.x;
    const int tx = tid & 15, ty = tid >> 4;

    float acc[4][4];
#pragma unroll
    for (int i = 0; i < 4; i++)
#pragma unroll
        for (int j = 0; j < 4; j++) acc[i][j] = 0.f;

    for (int k0 = 0; k0 < C_IN; k0 += 16) {
        {
            int oo = tid >> 2, kk = (tid & 3) * 4;
            const float* wp = &w[(size_t)(ob + oo) * C_IN + k0 + kk];
            float4 v = *(const float4*)wp;
            a_s[kk + 0][oo] = v.x; a_s[kk + 1][oo] = v.y;
            a_s[kk + 2][oo] = v.z; a_s[kk + 3][oo] = v.w;
        }
        {
            int kk = tid >> 4, ll = (tid & 15) * 4;
            const float4 v = *(const float4*)&xb[(size_t)(k0 + kk) * LPIX + lb + ll];
            b_s[kk][ll + 0] = v.x; b_s[kk][ll + 1] = v.y;
            b_s[kk][ll + 2] = v.z; b_s[kk][ll + 3] = v.w;
        }
        __syncthreads();
#pragma unroll
        for (int kk = 0; kk < 16; kk++) {
            float av[4], bv[4];
#pragma unroll
            for (int i = 0; i < 4; i++) av[i] = a_s[kk][ty * 4 + i];
#pragma unroll
            for (int j = 0; j < 4; j++) bv[j] = b_s[kk][tx * 4 + j];
#pragma unroll
            for (int i = 0; i < 4; i++)
#pragma unroll
                for (int j = 0; j < 4; j++) acc[i][j] += av[i] * bv[j];
        }
        __syncthreads();
    }

#pragma unroll
    for (int i = 0; i < 4; i++) {
        int o = ob + ty * 4 + i;
        float bb = bias[o];
        float* op = &g_value[((size_t)n * C4 + o) * LPIX + lb + tx * 4];
#pragma unroll
        for (int j = 0; j < 4; j++) op[j] = acc[i][j] + bb;
    }
}

// =========================================================================
// Kernel 2: pyramid pool -> rce conv -> q/k proj -> bilinear upsample
// =========================================================================
__global__ __launch_bounds__(256) void pyramid_kernel(
    const float* __restrict__ x,
    const float* __restrict__ rce_w, const float* __restrict__ rce_b,
    const float* __restrict__ q_w,   const float* __restrict__ q_b,
    const float* __restrict__ k_w,   const float* __restrict__ k_b)
{
    const int n = blockIdx.x, s = blockIdx.y;
    const int sz = 1 << s;            // 1, 2, 4
    const int bs = HDIM / sz;
    const int cells = sz * sz;
    const int tid = threadIdx.x;

    __shared__ float pooled_s[512 * 16];
    __shared__ float feat_s[128 * 16];
    __shared__ float qf_s[16 * 16];
    __shared__ float kf_s[16 * 16];

    // adaptive avg pool
    for (int c = tid; c < C_IN; c += 256) {
        const float* xp = x + ((size_t)n * C_IN + c) * LPIX;
        for (int ci = 0; ci < sz; ci++)
            for (int cj = 0; cj < sz; cj++) {
                float sum = 0.f;
                for (int a = 0; a < bs; a++) {
                    const float* rp = xp + (ci * bs + a) * HDIM + cj * bs;
                    for (int b = 0; b < bs; b++) sum += rp[b];
                }
                pooled_s[c * 16 + ci * sz + cj] = sum / (float)(bs * bs);
            }
    }
    __syncthreads();

    // rce 1x1 conv: C_IN -> C4 on pooled grid
    for (int idx = tid; idx < 128 * cells; idx += 256) {
        int o = idx & 127, cell = idx >> 7;
        const float* wp = rce_w + ((size_t)s * C4 + o) * C_IN;
        float sum = rce_b[s * C4 + o];
        for (int c = 0; c < C_IN; c++) sum += wp[c] * pooled_s[c * 16 + cell];
        feat_s[o * 16 + cell] = sum;
    }
    __syncthreads();

    // q/k 1x1 conv on pooled grid (commutes with upsample)
    for (int idx = tid; idx < QKC * cells; idx += 256) {
        int qc = idx & 15, cell = idx >> 4;
        const float* qwp = q_w + qc * C4;
        const float* kwp = k_w + qc * C4;
        float sq = q_b[qc], sk = k_b[qc];
        for (int c = 0; c < C4; c++) {
            float f = feat_s[c * 16 + cell];
            sq += qwp[c] * f;
            sk += kwp[c] * f;
        }
        qf_s[qc * 16 + cell] = sq;
        kf_s[qc * 16 + cell] = sk;
    }
    __syncthreads();

    // bilinear upsample (align_corners=True) to 32x32, write q/k
    float* gqb = g_q + (size_t)(n * NSCALE + s) * QKC * LPIX;
    float* gkb = g_k + (size_t)(n * NSCALE + s) * QKC * LPIX;

    for (int l = tid; l < LPIX; l += 256) {
        int o = l >> 5, p = l & 31;
        int io = 0, jo = 0;
        float fo = 0.f, fp = 0.f;
        if (sz > 1) {
            float pos = (float)o * (float)(sz - 1) / 31.0f;
            io = (int)pos; if (io > sz - 2) io = sz - 2;
            fo = pos - (float)io;
            pos = (float)p * (float)(sz - 1) / 31.0f;
            jo = (int)pos; if (jo > sz - 2) jo = sz - 2;
            fp = pos - (float)jo;
        }
        for (int qc = 0; qc < QKC; qc++) {
            float vq, vk;
            if (sz == 1) {
                vq = qf_s[qc * 16];
                vk = kf_s[qc * 16];
            } else {
                const float* f = &qf_s[qc * 16];
                float top = (1.f - fp) * f[io * sz + jo] + fp * f[io * sz + jo + 1];
                float bot = (1.f - fp) * f[(io + 1) * sz + jo] + fp * f[(io + 1) * sz + jo + 1];
                vq = (1.f - fo) * top + fo * bot;
                const float* g = &kf_s[qc * 16];
                top = (1.f - fp) * g[io * sz + jo] + fp * g[io * sz + jo + 1];
                bot = (1.f - fp) * g[(io + 1) * sz + jo] + fp * g[(io + 1) * sz + jo + 1];
                vk = (1.f - fo) * top + fo * bot;
            }
            gqb[qc * LPIX + l] = vq;
            gkb[qc * LPIX + l] = vk;
        }
    }
}

// =========================================================================
// Kernel 3: fused attention, tf32 mma, warp-owns-rows flash softmax.
// Block = 128 query rows; warp w owns rows [w*16, w*16+16) exclusively ->
// row max/sum/alpha are warp-local (quad shfl), P via warp-private smem
// strip + __syncwarp(). Only 2 __syncthreads per L-chunk (k/v staging).
// grid: (8 m-tiles, 3 scales, 16 batches), 256 threads.
// =========================================================================
__global__ __launch_bounds__(256) void attn_mma_kernel()
{
    const int m0 = blockIdx.x * 128;
    const int s  = blockIdx.y;
    const int n  = blockIdx.z;
    const int tid  = threadIdx.x;
    const int w    = tid >> 5;
    const int lane = tid & 31;
    const int g = lane >> 2, q = lane & 3;

    __shared__ float sm[9856];            // 39.4 KB
    float* k_s = sm;                      // [16][40]
    float* v_s = sm + 640;                // [128][36]
    float* p_s = sm + 5248;               // [128][36] (warp strips of 16 rows)
    float* out_s = sm;                    // alias [128][66] for epilogue

    const float* qb = g_q + (size_t)(n * NSCALE + s) * QKC * LPIX;
    const float* kb = g_k + (size_t)(n * NSCALE + s) * QKC * LPIX;
    const float* vb = g_value + (size_t)n * C4 * LPIX;

    // persistent q A-fragments for this warp's 16 rows (2 k-steps)
    const int rlo = m0 + w * 16 + g;
    float qa[2][4];
#pragma unroll
    for (int ks = 0; ks < 2; ks++) {
        qa[ks][0] = tf32r(qb[(ks * 8 + q) * LPIX + rlo]);
        qa[ks][1] = tf32r(qb[(ks * 8 + q) * LPIX + rlo + 8]);
        qa[ks][2] = tf32r(qb[(ks * 8 + q + 4) * LPIX + rlo]);
        qa[ks][3] = tf32r(qb[(ks * 8 + q + 4) * LPIX + rlo + 8]);
    }

    float M0 = -1e30f, M1 = -1e30f, S0 = 0.f, S1 = 0.f;
    float acc[16][4];
#pragma unroll
    for (int nt = 0; nt < 16; nt++)
#pragma unroll
        for (int r = 0; r < 4; r++) acc[nt][r] = 0.f;

    float* pw = p_s + w * 16 * 36;        // warp-private P strip

    for (int l0 = 0; l0 < LPIX; l0 += 32) {
        __syncthreads();                  // protect k_s/v_s from prev iter
        // ---- stage k [16][32] and v [128][32], float4, tf32-rounded ----
        if (tid < 128) {
            int kc = tid >> 3, l4 = (tid & 7) * 4;
            float4 t = *(const float4*)&kb[kc * LPIX + l0 + l4];
            float4 r4 = make_float4(tf32r(t.x), tf32r(t.y), tf32r(t.z), tf32r(t.w));
            *(float4*)&k_s[kc * 40 + l4] = r4;
        }
#pragma unroll
        for (int e = tid; e < 1024; e += 256) {
            int c = e >> 3, l4 = (e & 7) * 4;
            float4 t = *(const float4*)&vb[(size_t)c * LPIX + l0 + l4];
            float4 r4 = make_float4(tf32r(t.x), tf32r(t.y), tf32r(t.z), tf32r(t.w));
            *(float4*)&v_s[c * 36 + l4] = r4;
        }
        __syncthreads();

        // ---- QK: this warp's 16 rows x all 32 l-cols (4 n-tiles) ----
        float sacc[4][4];
#pragma unroll
        for (int nt = 0; nt < 4; nt++) {
            sacc[nt][0] = sacc[nt][1] = sacc[nt][2] = sacc[nt][3] = 0.f;
#pragma unroll
            for (int ks = 0; ks < 2; ks++) {
                float b0 = k_s[(ks * 8 + q) * 40 + nt * 8 + g];
                float b1 = k_s[(ks * 8 + q + 4) * 40 + nt * 8 + g];
                mma_tf32(sacc[nt], qa[ks], b0, b1);
            }
        }

        // ---- warp-local row max via quad shfl ----
        float mx0 = -1e30f, mx1 = -1e30f;
#pragma unroll
        for (int nt = 0; nt < 4; nt++) {
            mx0 = fmaxf(mx0, fmaxf(sacc[nt][0], sacc[nt][1]));
            mx1 = fmaxf(mx1, fmaxf(sacc[nt][2], sacc[nt][3]));
        }
        mx0 = fmaxf(mx0, __shfl_xor_sync(0xffffffffu, mx0, 1));
        mx0 = fmaxf(mx0, __shfl_xor_sync(0xffffffffu, mx0, 2));
        mx1 = fmaxf(mx1, __shfl_xor_sync(0xffffffffu, mx1, 1));
        mx1 = fmaxf(mx1, __shfl_xor_sync(0xffffffffu, mx1, 2));

        float Mn0 = fmaxf(M0, mx0), Mn1 = fmaxf(M1, mx1);
        float a0 = __expf(M0 - Mn0), a1 = __expf(M1 - Mn1);
        M0 = Mn0; M1 = Mn1;

        // ---- exp, write P to warp strip, row sums ----
        float ps0 = 0.f, ps1 = 0.f;
#pragma unroll
        for (int nt = 0; nt < 4; nt++) {
            float e00 = __expf(sacc[nt][0] - M0);
            float e01 = __expf(sacc[nt][1] - M0);
            float e10 = __expf(sacc[nt][2] - M1);
            float e11 = __expf(sacc[nt][3] - M1);
            ps0 += e00 + e01;
            ps1 += e10 + e11;
            int col = nt * 8 + 2 * q;
            *(float2*)&pw[g * 36 + col]       = make_float2(tf32r(e00), tf32r(e01));
            *(float2*)&pw[(g + 8) * 36 + col] = make_float2(tf32r(e10), tf32r(e11));
        }
        ps0 += __shfl_xor_sync(0xffffffffu, ps0, 1);
        ps0 += __shfl_xor_sync(0xffffffffu, ps0, 2);
        ps1 += __shfl_xor_sync(0xffffffffu, ps1, 1);
        ps1 += __shfl_xor_sync(0xffffffffu, ps1, 2);
        S0 = S0 * a0 + ps0;
        S1 = S1 * a1 + ps1;

        // ---- rescale accumulators ----
#pragma unroll
        for (int nt = 0; nt < 16; nt++) {
            acc[nt][0] *= a0; acc[nt][1] *= a0;
            acc[nt][2] *= a1; acc[nt][3] *= a1;
        }
        __syncwarp();

        // ---- PV: D[16m x 128c] per warp ----
#pragma unroll
        for (int ks = 0; ks < 4; ks++) {
            float pa[4];
            pa[0] = pw[g * 36 + ks * 8 + q];
            pa[1] = pw[(g + 8) * 36 + ks * 8 + q];
            pa[2] = pw[g * 36 + ks * 8 + q + 4];
            pa[3] = pw[(g + 8) * 36 + ks * 8 + q + 4];
#pragma unroll
            for (int nt = 0; nt < 16; nt++) {
                float b0 = v_s[(nt * 8 + g) * 36 + ks * 8 + q];
                float b1 = v_s[(nt * 8 + g) * 36 + ks * 8 + q + 4];
                mma_tf32(acc[nt], pa, b0, b1);
            }
        }
    }

    // ---- epilogue: normalize, transpose via smem in 2 waves ----
    float il = 1.f / S0, ih = 1.f / S1;
    float* cb = g_cat + ((size_t)n * (NSCALE * C4) + s * C4) * LPIX + m0;
#pragma unroll
    for (int wave = 0; wave < 2; wave++) {
        __syncthreads();     // smem free (prev wave copy / main loop done)
        if ((w >> 2) == wave) {
            int lm = (w & 3) * 16 + g;        // 0..63 within wave
#pragma unroll
            for (int nt = 0; nt < 16; nt++) {
                int c = nt * 8 + 2 * q;
                out_s[(size_t)c * 66 + lm]       = acc[nt][0] * il;
                out_s[(size_t)(c + 1) * 66 + lm] = acc[nt][1] * il;
                out_s[(size_t)c * 66 + lm + 8]       = acc[nt][2] * ih;
                out_s[(size_t)(c + 1) * 66 + lm + 8] = acc[nt][3] * ih;
            }
        }
        __syncthreads();
        for (int e = tid; e < 8192; e += 256) {
            int c = e >> 6, m = e & 63;
            cb[(size_t)c * LPIX + wave * 64 + m] = out_s[c * 66 + m];
        }
    }
}

// =========================================================================
// Kernel 4a: weight transform  g_wt[p][ic][oc] = tf32(fusion_w[oc][ic][p])
// =========================================================================
__global__ __launch_bounds__(256) void wt_transform_kernel(const float* __restrict__ W)
{
    int idx = blockIdx.x * 256 + threadIdx.x;   // total 9*384*512 = 1769472
    if (idx >= 9 * 384 * 512) return;
    int oc = idx & 511;
    int t  = idx >> 9;
    int ic = t % 384;
    int p  = t / 384;
    g_wt[idx] = tf32r(W[(size_t)oc * 3456 + ic * 9 + p]);
}

// =========================================================================
// Kernel 4b: 3x3 fusion conv as implicit GEMM with tf32 mma.sync m16n8k8.
// =========================================================================
__global__ __launch_bounds__(256, 2) void conv_mma_kernel()
{
    const int ocb = blockIdx.x * 64;
    const int h0  = blockIdx.y * 8;
    const int n   = blockIdx.z;
    const int tid  = threadIdx.x;
    const int wid  = tid >> 5;
    const int lane = tid & 31;
    const int g = lane >> 2;       // group id 0..7
    const int q = lane & 3;        // thread-in-group 0..3
    const int wm = wid >> 2;       // 0..1 (oc)
    const int wn = wid & 3;        // 0..3 (pixel rows pair)

    __shared__ float in_s[8 * 344];      // [ic 8][(row 10)*(col 34) pad 344]
    __shared__ float a_s[9 * 64 * 12];   // [p 9][oc 64][ic 8 pad 12]

    float acc[2][8][4];
#pragma unroll
    for (int mt = 0; mt < 2; mt++)
#pragma unroll
        for (int nt = 0; nt < 8; nt++)
#pragma unroll
            for (int r = 0; r < 4; r++) acc[mt][nt][r] = 0.f;

    const float* catn = g_cat + (size_t)n * (NSCALE * C4) * LPIX;

    for (int ic0 = 0; ic0 < 384; ic0 += 8) {
        for (int e = tid; e < 8 * 340; e += 256) {
            int ic  = e / 340;
            int rem = e - ic * 340;
            int rr  = rem / 34;
            int cc  = rem - rr * 34;
            int gh = h0 + rr - 1, gw = cc - 1;
            float v = 0.f;
            if ((unsigned)gh < 32u && (unsigned)gw < 32u)
                v = catn[(size_t)(ic0 + ic) * LPIX + gh * HDIM + gw];
            in_s[ic * 344 + rem] = tf32r(v);
        }
        for (int e = tid; e < 4608; e += 256) {
            int o = e & 63;
            int t = e >> 6;
            int i = t & 7;
            int p = t >> 3;
            a_s[(p * 64 + o) * 12 + i] = g_wt[((size_t)p * 384 + ic0 + i) * 512 + ocb + o];
        }
        __syncthreads();

#pragma unroll
        for (int p = 0; p < 9; p++) {
            const int kh = p / 3, kw = p - kh * 3;
            float afr[2][4];
#pragma unroll
            for (int mt = 0; mt < 2; mt++) {
                const float* ab = &a_s[(p * 64 + wm * 32 + mt * 16) * 12];
                afr[mt][0] = ab[g * 12 + q];
                afr[mt][1] = ab[(g + 8) * 12 + q];
                afr[mt][2] = ab[g * 12 + q + 4];
                afr[mt][3] = ab[(g + 8) * 12 + q + 4];
            }
#pragma unroll
            for (int nt = 0; nt < 8; nt++) {
                const int lh = wn * 2 + (nt >> 2);
                const int off = (lh + kh) * 34 + (nt & 3) * 8 + g + kw;
                float b0 = in_s[q * 344 + off];
                float b1 = in_s[(q + 4) * 344 + off];
                mma_tf32(acc[0][nt], afr[0], b0, b1);
                mma_tf32(acc[1][nt], afr[1], b0, b1);
            }
        }
        __syncthreads();
    }

    float* yb = g_y + (size_t)n * C_IN * LPIX;
#pragma unroll
    for (int mt = 0; mt < 2; mt++) {
        int oc0 = ocb + wm * 32 + mt * 16 + g;
#pragma unroll
        for (int nt = 0; nt < 8; nt++) {
            int px = h0 * HDIM + wn * 64 + nt * 8 + 2 * q;
            *(float2*)&yb[(size_t)oc0 * LPIX + px] =
                make_float2(acc[mt][nt][0], acc[mt][nt][1]);
            *(float2*)&yb[(size_t)(oc0 + 8) * LPIX + px] =
                make_float2(acc[mt][nt][2], acc[mt][nt][3]);
        }
    }
}

// =========================================================================
// Kernel 5: BN batch stats per channel (over N,H,W = 16384 values)
// =========================================================================
__global__ __launch_bounds__(256) void bn_stats_kernel(const float* __restrict__ bn_scale)
{
    const int c = blockIdx.x;
    const int tid = threadIdx.x;
    float s = 0.f, sq = 0.f;
    for (int n = 0; n < N_B; n++) {
        const float* p = g_y + ((size_t)n * C_IN + c) * LPIX;
        for (int l = tid; l < LPIX; l += 256) {
            float v = p[l];
            s += v;
            sq += v * v;
        }
    }
    __shared__ float r1[256], r2[256];
    r1[tid] = s; r2[tid] = sq;
    __syncthreads();
    for (int off = 128; off > 0; off >>= 1) {
        if (tid < off) { r1[tid] += r1[tid + off]; r2[tid] += r2[tid + off]; }
        __syncthreads();
    }
    if (tid == 0) {
        float m = r1[0] / 16384.f;
        float var = r2[0] / 16384.f - m * m;
        g_mean[c] = m;
        g_rstd[c] = bn_scale[c] / sqrtf(var + EPSBN);
    }
}

// =========================================================================
// Kernel 6: BN apply + ReLU + gamma*y + x   (float4 elementwise)
// =========================================================================
__global__ __launch_bounds__(256) void final_kernel(
    const float* __restrict__ x, const float* __restrict__ bn_bias,
    const float* __restrict__ gammap, float* __restrict__ out)
{
    const float gamma = gammap[0];
    int idx4 = blockIdx.x * blockDim.x + threadIdx.x;   // 2097152 total
    int c = (idx4 >> 8) & 511;
    float mean = g_mean[c], rstd = g_rstd[c], bias = bn_bias[c];
    float4 y = *(const float4*)&g_y[(size_t)idx4 * 4];
    float4 xv = *(const float4*)&x[(size_t)idx4 * 4];
    float4 o;
    o.x = gamma * fmaxf((y.x - mean) * rstd + bias, 0.f) + xv.x;
    o.y = gamma * fmaxf((y.y - mean) * rstd + bias, 0.f) + xv.y;
    o.z = gamma * fmaxf((y.z - mean) * rstd + bias, 0.f) + xv.z;
    o.w = gamma * fmaxf((y.w - mean) * rstd + bias, 0.f) + xv.w;
    *(float4*)&out[(size_t)idx4 * 4] = o;
}

// =========================================================================
extern "C" void kernel_launch(void* const* d_in, const int* in_sizes, int n_in,
                              void* d_out, int out_size)
{
    const float* x        = (const float*)d_in[0];
    const float* rce_w    = (const float*)d_in[1];
    const float* rce_b    = (const float*)d_in[2];
    const float* q_w      = (const float*)d_in[3];
    const float* q_b      = (const float*)d_in[4];
    const float* k_w      = (const float*)d_in[5];
    const float* k_b      = (const float*)d_in[6];
    const float* value_w  = (const float*)d_in[7];
    const float* value_b  = (const float*)d_in[8];
    const float* fusion_w = (const float*)d_in[9];
    const float* bn_scale = (const float*)d_in[10];
    const float* bn_bias  = (const float*)d_in[11];
    const float* gamma    = (const float*)d_in[12];
    float* out = (float*)d_out;

    value_proj_kernel<<<dim3(16, 2, 16), 256>>>(x, value_w, value_b);
    pyramid_kernel<<<dim3(16, 3), 256>>>(x, rce_w, rce_b, q_w, q_b, k_w, k_b);
    wt_transform_kernel<<<dim3((9 * 384 * 512 + 255) / 256), 256>>>(fusion_w);
    attn_mma_kernel<<<dim3(8, 3, 16), 256>>>();
    conv_mma_kernel<<<dim3(8, 4, 16), 256>>>();
    bn_stats_kernel<<<dim3(512), 256>>>(bn_scale);
    final_kernel<<<dim3(8192), 256>>>(x, bn_bias, gamma, out);
}